// round 16
// baseline (speedup 1.0000x reference)
#include <cuda_runtime.h>
#include <math.h>

#define NB 16
#define NI 1024
#define NO 64
#define CH 64
#define EPSV 1e-5f
#define TILE 32      // i's per k_iter block -> NB*32 = 512 blocks
#define TILE0 32     // i's per k_iter0 block -> 512 blocks

typedef unsigned long long ull;

// V row layout (per b,i): ch' = c*1024 + j*16 + h (c-major) so thread t
// accesses offset c*1024 + t*4 -> warp-contiguous.
__device__ float g_V[(size_t)NB * NI * NO * CH];   // 256 MB
__device__ float g_S1b[3][NB * NO * CH];           // c-major layout per b
__device__ float g_S2b[3][NB * NO * CH];
__device__ float g_S0b[3][NB * NO];
__device__ float g_aoutb[3][NB * NO];
__device__ float g_nA[NB * NO * CH];               // -1/(2 sig2), c-major
__device__ float g_G[NB * NO * CH];                // mu/sig2,   c-major
__device__ float g_lac0[NB * NO];                  // log_sigmoid(a) - c0

// ---------------- f32x2 helpers ----------------
__device__ __forceinline__ ull pack2(float lo, float hi) {
    ull r; asm("mov.b64 %0, {%1, %2};" : "=l"(r) : "f"(lo), "f"(hi)); return r;
}
__device__ __forceinline__ void unpack2(ull v, float& lo, float& hi) {
    asm("mov.b64 {%0, %1}, %2;" : "=f"(lo), "=f"(hi) : "l"(v));
}
__device__ __forceinline__ ull fma2_3(ull a, ull b, ull c) {
    ull d; asm("fma.rn.f32x2 %0, %1, %2, %3;" : "=l"(d) : "l"(a), "l"(b), "l"(c)); return d;
}
__device__ __forceinline__ ull mul2(ull a, ull b) {
    ull d; asm("mul.rn.f32x2 %0, %1, %2;" : "=l"(d) : "l"(a), "l"(b)); return d;
}
__device__ __forceinline__ ull add2(ull a, ull b) {
    ull d; asm("add.rn.f32x2 %0, %1, %2;" : "=l"(d) : "l"(a), "l"(b)); return d;
}
__device__ __forceinline__ void fma2(ull& d, ull a, ull b) {
    asm("fma.rn.f32x2 %0, %1, %2, %0;" : "+l"(d) : "l"(a), "l"(b));
}

__global__ void k_zero() {
    int idx = blockIdx.x * 256 + threadIdx.x;
    if (idx < 3 * NB * NO * CH) {
        ((float*)g_S1b)[idx] = 0.f;
        ((float*)g_S2b)[idx] = 0.f;
    }
    if (idx < 3 * NB * NO) {
        ((float*)g_S0b)[idx] = 0.f;
        ((float*)g_aoutb)[idx] = 0.f;
    }
}

// ---------------- V generation ----------------
// Latency-bound fix: accumulation chains split in two (16 independent chains
// with unroll 4), As2 read as 128-bit pairs (half the LDS issues), B resident
// in smem (register relief), occupancy pinned at 2 blocks/SM.
__global__ __launch_bounds__(256, 2) void k_computeV(const float* __restrict__ mu,
                                                     const float* __restrict__ W,
                                                     const float* __restrict__ Bp) {
    int i = blockIdx.x;
    int t = threadIdx.x;
    __shared__ ull As2[64][16];      // 8 KB, [m=(b*4+c)][d], both halves = mu
    __shared__ float SB[9216];       // 36 KB staging (W halves, then B resident)

    for (int e = t; e < 1024; e += 256) {
        int m = e >> 4, d = e & 15;
        int b = m >> 2, c = m & 3;
        float val = mu[((size_t)b * NI + i) * 64 + c * 16 + d];
        As2[m][d] = pack2(val, val);
    }

    int j = t >> 2;
    int q = t & 3;
    float4* SB4 = (float4*)SB;

    // ---- stage W in two halves: layout [j][dd][h], row stride 144 floats ----
    ull w01[16], w23[16];
    const float4* Wi4 = (const float4*)(W + (size_t)i * 16384);
    #pragma unroll
    for (int half = 0; half < 2; half++) {
        for (int idx = t; idx < 2048; idx += 256) {
            int jj = idx >> 5, rem = idx & 31;     // rem = dd*4 + h4
            SB4[jj * 36 + rem] = Wi4[jj * 64 + half * 32 + rem];
        }
        __syncthreads();
        #pragma unroll
        for (int dd = 0; dd < 8; dd++) {
            float4 w4 = *(const float4*)(SB + j * 144 + dd * 16 + q * 4);
            int d = half * 8 + dd;
            w01[d] = pack2(w4.x, w4.y);
            w23[d] = pack2(w4.z, w4.w);
        }
        __syncthreads();
    }

    // ---- stage B into SB (resident through the m-loop): [j][c][h], stride 80 ----
    {
        const float4* Bp4 = (const float4*)(Bp + (size_t)i * 4096);
        for (int idx = t; idx < 1024; idx += 256) {
            int jj = idx >> 4, rem = idx & 15;     // rem = c*4 + h4
            SB4[jj * 20 + rem] = Bp4[idx];
        }
    }
    __syncthreads();

    #pragma unroll 4
    for (int m = 0; m < 64; m++) {
        int bb = m >> 2, c = m & 3;
        float4 b4 = *(const float4*)(SB + j * 80 + c * 16 + q * 4);
        ull a0  = pack2(b4.x, b4.y);
        ull a1  = pack2(b4.z, b4.w);
        ull a0b = pack2(0.f, 0.f);
        ull a1b = pack2(0.f, 0.f);
        // chain half 1: d = 0..7 (As2 pairs via 128-bit loads)
        #pragma unroll
        for (int dp = 0; dp < 4; dp++) {
            ulonglong2 aa2 = *(const ulonglong2*)&As2[m][dp * 2];
            fma2(a0, aa2.x, w01[2*dp]);     fma2(a1, aa2.x, w23[2*dp]);
            fma2(a0, aa2.y, w01[2*dp + 1]); fma2(a1, aa2.y, w23[2*dp + 1]);
        }
        // chain half 2: d = 8..15 into independent accumulators
        #pragma unroll
        for (int dp = 4; dp < 8; dp++) {
            ulonglong2 aa2 = *(const ulonglong2*)&As2[m][dp * 2];
            fma2(a0b, aa2.x, w01[2*dp]);     fma2(a1b, aa2.x, w23[2*dp]);
            fma2(a0b, aa2.y, w01[2*dp + 1]); fma2(a1b, aa2.y, w23[2*dp + 1]);
        }
        a0 = add2(a0, a0b);
        a1 = add2(a1, a1b);
        float4 r;
        unpack2(a0, r.x, r.y);
        unpack2(a1, r.z, r.w);
        size_t off = (size_t)bb * (NI * 4096ull) + (size_t)i * 4096
                   + (size_t)c * 1024 + (size_t)j * 16 + q * 4;   // c-major row
        *(float4*)(g_V + off) = r;
    }
}

// load this thread's 16 channels of a row: 4 coalesced float4 at c*1024 + t*4
__device__ __forceinline__ void load_row2(ull v[8], const float* row, int t) {
    #pragma unroll
    for (int c = 0; c < 4; c++) {
        float4 x = *(const float4*)(row + c * 1024 + t * 4);
        v[2*c]   = pack2(x.x, x.y);
        v[2*c+1] = pack2(x.z, x.w);
    }
}
__device__ __forceinline__ float sigmoidf_(float x) {
    return 1.f / (1.f + __expf(-x));
}

// ---------------- iteration 0: uniform R, tiles REVERSED (L2 zigzag) -------
__global__ __launch_bounds__(256) void k_iter0(const float* __restrict__ a_inp,
                                               const float* __restrict__ beta_use,
                                               const float* __restrict__ beta_ign) {
    int b    = blockIdx.x >> 5;
    int tile = 31 - (blockIdx.x & 31);   // reverse: start on freshest V
    int t    = threadIdx.x;

    __shared__ float bUs[TILE0 * 64], bIs[TILE0 * 64];   // 16 KB beta slice
    {
        const float4* bu4 = (const float4*)(beta_use + tile * TILE0 * 64);
        const float4* bi4 = (const float4*)(beta_ign + tile * TILE0 * 64);
        float4* u4 = (float4*)bUs; float4* i4 = (float4*)bIs;
        for (int idx = t; idx < TILE0 * 16; idx += 256) {
            u4[idx] = bu4[idx];
            i4[idx] = bi4[idx];
        }
    }
    __syncthreads();

    ull s1a[8], s2a[8];
    #pragma unroll
    for (int c = 0; c < 8; c++) { s1a[c] = pack2(0.f, 0.f); s2a[c] = s1a[c]; }
    float s0p = 0.f, aop = 0.f;

    const float* vb0 = g_V + (size_t)b * (NI * 4096ull);
    #pragma unroll 2
    for (int il = TILE0 - 1; il >= 0; il--) {    // descending i within tile
        int i = tile * TILE0 + il;
        ull v[8];
        load_row2(v, vb0 + (size_t)i * 4096, t);
        float fa = sigmoidf_(a_inp[b * NI + i]);
        float d = fa * (1.f / 64.f);
        ull d2 = pack2(d, d);
        #pragma unroll
        for (int c = 0; c < 8; c++) {
            fma2(s1a[c], v[c], d2);
            ull w = mul2(v[c], d2);
            fma2(s2a[c], w, v[c]);
        }
        if (t < 64) {
            s0p += d;
            aop += bUs[il * 64 + t] * d - bIs[il * 64 + t] * (fa - d);
        }
    }
    float* s1g = g_S1b[0] + b * 4096;
    float* s2g = g_S2b[0] + b * 4096;
    #pragma unroll
    for (int c = 0; c < 4; c++) {
        float lo, hi;
        int base = c * 1024 + t * 4;
        unpack2(s1a[2*c], lo, hi);
        atomicAdd(s1g + base + 0, lo); atomicAdd(s1g + base + 1, hi);
        unpack2(s1a[2*c+1], lo, hi);
        atomicAdd(s1g + base + 2, lo); atomicAdd(s1g + base + 3, hi);
        unpack2(s2a[2*c], lo, hi);
        atomicAdd(s2g + base + 0, lo); atomicAdd(s2g + base + 1, hi);
        unpack2(s2a[2*c+1], lo, hi);
        atomicAdd(s2g + base + 2, lo); atomicAdd(s2g + base + 3, hi);
    }
    if (t < 64) {
        atomicAdd(g_S0b[0] + b * 64 + t, s0p);
        atomicAdd(g_aoutb[0] + b * 64 + t, aop);
    }
}

// ---------------- coefficient kernel: bank SRC -> (-A, G, la-c0) ----------------
template<int SRC>
__global__ void k_coeff() {
    int bj = blockIdx.x;
    int b  = bj >> 6, j = bj & 63;
    int ch = threadIdx.x;
    int c  = ch >> 4, h = ch & 15;
    int idx = b * 4096 + c * 1024 + j * 16 + h;
    float S0 = g_S0b[SRC][bj];
    float over = 1.f / (S0 + EPSV);
    float s1 = g_S1b[SRC][idx];
    float s2 = g_S2b[SRC][idx];
    float m  = s1 * over;
    float sig2 = (s2 - 2.f * m * s1 + m * m * S0) * over + EPSV;
    float A = 0.5f / sig2;
    g_nA[idx] = -A;
    g_G[idx]  = m / sig2;
    float cc = m * m * A + 0.5f * logf(sig2);
    #pragma unroll
    for (int o = 16; o; o >>= 1) cc += __shfl_xor_sync(0xffffffffu, cc, o);
    __shared__ float red[2];
    if ((ch & 31) == 0) red[ch >> 5] = cc;
    __syncthreads();
    if (ch == 0) {
        float a = g_aoutb[SRC][bj];
        float la = fminf(a, 0.f) - log1pf(__expf(-fabsf(a)));
        g_lac0[bj] = la - (red[0] + red[1]);
    }
}

// logit partial over this thread's 16 channels (two 4-deep chains)
__device__ __forceinline__ float logit_part(const ull v[8], const ull nA2[8],
                                            const ull G2[8]) {
    ull s  = pack2(0.f, 0.f);
    ull s2 = pack2(0.f, 0.f);
    #pragma unroll
    for (int cp = 0; cp < 4; cp++) {
        ull tt = fma2_3(v[cp], nA2[cp], G2[cp]);
        s = fma2_3(v[cp], tt, s);
    }
    #pragma unroll
    for (int cp = 4; cp < 8; cp++) {
        ull tt = fma2_3(v[cp], nA2[cp], G2[cp]);
        s2 = fma2_3(v[cp], tt, s2);
    }
    s = add2(s, s2);
    float lo, hi; unpack2(s, lo, hi);
    float r = lo + hi;
    r += __shfl_xor_sync(0xffffffffu, r, 1);
    r += __shfl_xor_sync(0xffffffffu, r, 2);
    return r;
}

// ---------------- iterations 1,2 (REV selects tile traversal direction) ------
// zigzag chain: computeV(i up) -> iter0(i down) -> iter1(i up) -> iter2(i down)
template<int IT, int REV>
__global__ __launch_bounds__(256) void k_iter(const float* __restrict__ a_inp,
                                              const float* __restrict__ beta_use,
                                              const float* __restrict__ beta_ign) {
    int b    = blockIdx.x >> 5;
    int tl   = blockIdx.x & 31;
    int tile = REV ? (31 - tl) : tl;
    int t    = threadIdx.x;
    int j4   = t >> 2;
    int part = t & 3;
    int lane = t & 31;

    __shared__ float lbuf[2][2][64];
    __shared__ float bUs[TILE * 64], bIs[TILE * 64];    // 16 KB beta slice

    int ibase = tile * TILE;
    {
        const float4* bu4 = (const float4*)(beta_use + ibase * 64);
        const float4* bi4 = (const float4*)(beta_ign + ibase * 64);
        float4* u4 = (float4*)bUs; float4* i4 = (float4*)bIs;
        for (int idx = t; idx < TILE * 16; idx += 256) {
            u4[idx] = bu4[idx];
            i4[idx] = bi4[idx];
        }
    }

    ull nA2[8], G2[8];
    {
        const float* Ap = g_nA + b * 4096;
        const float* Gp = g_G + b * 4096;
        #pragma unroll
        for (int c = 0; c < 4; c++) {
            float4 av = *(const float4*)(Ap + c * 1024 + t * 4);
            float4 gv = *(const float4*)(Gp + c * 1024 + t * 4);
            nA2[2*c]   = pack2(av.x, av.y);
            nA2[2*c+1] = pack2(av.z, av.w);
            G2[2*c]    = pack2(gv.x, gv.y);
            G2[2*c+1]  = pack2(gv.z, gv.w);
        }
    }
    float lac0 = g_lac0[b * 64 + j4];

    ull s1a[8], s2a[8];
    #pragma unroll
    for (int c = 0; c < 8; c++) { s1a[c] = pack2(0.f, 0.f); s2a[c] = s1a[c]; }
    float s0p = 0.f, aop = 0.f;

    const float* vb0 = g_V + (size_t)b * (NI * 4096ull);

    ull va[8], vb[8];
    float faA, faB;
    load_row2(va, vb0 + (size_t)ibase * 4096, t);
    load_row2(vb, vb0 + (size_t)(ibase + 1) * 4096, t);
    faA = sigmoidf_(a_inp[b * NI + ibase]);
    faB = sigmoidf_(a_inp[b * NI + ibase + 1]);
    __syncthreads();   // beta staging visible before first tail use

    #pragma unroll 1
    for (int p = 0; p < TILE / 2; p++) {
        int iA = ibase + 2 * p;
        int iB = iA + 1;
        int pb = p & 1;
        float fcA = faA, fcB = faB;

        float lA = logit_part(va, nA2, G2);
        float lB = logit_part(vb, nA2, G2);
        if (part == 0) { lbuf[pb][0][j4] = lA + lac0; lbuf[pb][1][j4] = lB + lac0; }
        __syncthreads();

        float a0 = lbuf[pb][0][lane], a1 = lbuf[pb][0][lane + 32];
        float b0 = lbuf[pb][1][lane], b1 = lbuf[pb][1][lane + 32];
        float mxA = fmaxf(a0, a1), mxB = fmaxf(b0, b1);
        #pragma unroll
        for (int o = 16; o; o >>= 1) {
            mxA = fmaxf(mxA, __shfl_xor_sync(0xffffffffu, mxA, o));
            mxB = fmaxf(mxB, __shfl_xor_sync(0xffffffffu, mxB, o));
        }
        float ssA = __expf(a0 - mxA) + __expf(a1 - mxA);
        float ssB = __expf(b0 - mxB) + __expf(b1 - mxB);
        #pragma unroll
        for (int o = 16; o; o >>= 1) {
            ssA += __shfl_xor_sync(0xffffffffu, ssA, o);
            ssB += __shfl_xor_sync(0xffffffffu, ssB, o);
        }
        float invA = fcA / ssA, invB = fcB / ssB;
        float dA = __expf(lbuf[pb][0][j4] - mxA) * invA;
        float dB = __expf(lbuf[pb][1][j4] - mxB) * invB;

        if (t < 64) {
            float duA = __expf(lbuf[pb][0][t] - mxA) * invA;
            float duB = __expf(lbuf[pb][1][t] - mxB) * invB;
            s0p += duA + duB;
            int r0 = 2 * p * 64 + t, r1 = r0 + 64;
            aop += bUs[r0] * duA - bIs[r0] * (fcA - duA)
                 + bUs[r1] * duB - bIs[r1] * (fcB - duB);
        }

        int nxt = (p < TILE / 2 - 1) ? iA + 2 : ibase;
        {
            ull d2 = pack2(dA, dA);
            #pragma unroll
            for (int c = 0; c < 8; c++) {
                fma2(s1a[c], va[c], d2);
                ull w = mul2(va[c], d2);
                fma2(s2a[c], w, va[c]);
            }
        }
        load_row2(va, vb0 + (size_t)nxt * 4096, t);
        faA = sigmoidf_(a_inp[b * NI + nxt]);

        {
            ull d2 = pack2(dB, dB);
            #pragma unroll
            for (int c = 0; c < 8; c++) {
                fma2(s1a[c], vb[c], d2);
                ull w = mul2(vb[c], d2);
                fma2(s2a[c], w, vb[c]);
            }
        }
        load_row2(vb, vb0 + (size_t)(nxt + 1) * 4096, t);
        faB = sigmoidf_(a_inp[b * NI + nxt + 1]);
    }

    float* s1g = g_S1b[IT] + b * 4096;
    float* s2g = g_S2b[IT] + b * 4096;
    #pragma unroll
    for (int c = 0; c < 4; c++) {
        float lo, hi;
        int base = c * 1024 + t * 4;
        unpack2(s1a[2*c], lo, hi);
        atomicAdd(s1g + base + 0, lo); atomicAdd(s1g + base + 1, hi);
        unpack2(s1a[2*c+1], lo, hi);
        atomicAdd(s1g + base + 2, lo); atomicAdd(s1g + base + 3, hi);
        unpack2(s2a[2*c], lo, hi);
        atomicAdd(s2g + base + 0, lo); atomicAdd(s2g + base + 1, hi);
        unpack2(s2a[2*c+1], lo, hi);
        atomicAdd(s2g + base + 2, lo); atomicAdd(s2g + base + 3, hi);
    }
    if (t < 64) {
        atomicAdd(g_S0b[IT] + b * 64 + t, s0p);
        atomicAdd(g_aoutb[IT] + b * 64 + t, aop);
    }
}

// ---------------- final output from bank 2 (remap c-major -> j,c,h) ----------
__global__ void k_final(float* __restrict__ out) {
    int bj = blockIdx.x;
    int b  = bj >> 6, j = bj & 63;
    int ch = threadIdx.x;
    int c  = ch >> 4, h = ch & 15;
    int idx = b * 4096 + c * 1024 + j * 16 + h;
    float S0 = g_S0b[2][bj];
    float over = 1.f / (S0 + EPSV);
    float s1 = g_S1b[2][idx];
    float s2 = g_S2b[2][idx];
    float m  = s1 * over;
    float sig2 = (s2 - 2.f * m * s1 + m * m * S0) * over + EPSV;
    if (ch == 0) out[bj] = g_aoutb[2][bj];
    out[1024 + bj * 64 + ch] = m;
    out[1024 + NB * NO * CH + bj * 64 + ch] = sig2;
}

extern "C" void kernel_launch(void* const* d_in, const int* in_sizes, int n_in,
                              void* d_out, int out_size) {
    const float* a_inp = (const float*)d_in[0];
    const float* mu    = (const float*)d_in[1];
    const float* W     = (const float*)d_in[2];
    const float* Bp    = (const float*)d_in[3];
    const float* bu    = (const float*)d_in[4];
    const float* bi    = (const float*)d_in[5];
    float* out = (float*)d_out;

    k_zero<<<(3 * NB * NO * CH) / 256 + 1, 256>>>();
    k_computeV<<<NI, 256>>>(mu, W, Bp);          // writes V, i ascending
    k_iter0<<<NB * (NI / TILE0), 256>>>(a_inp, bu, bi);   // reads V, descending
    k_coeff<0><<<NB * NO, 64>>>();
    k_iter<1, 0><<<NB * (NI / TILE), 256>>>(a_inp, bu, bi); // ascending
    k_coeff<1><<<NB * NO, 64>>>();
    k_iter<2, 1><<<NB * (NI / TILE), 256>>>(a_inp, bu, bi); // descending
    k_final<<<NB * NO, 64>>>(out);
}

// round 17
// speedup vs baseline: 1.0446x; 1.0446x over previous
#include <cuda_runtime.h>
#include <math.h>

#define NB 16
#define NI 1024
#define NO 64
#define CH 64
#define EPSV 1e-5f
#define TILE 32      // i's per k_iter block -> NB*32 = 512 blocks
#define TILE0 32     // i's per k_iter0 block -> 512 blocks

typedef unsigned long long ull;

// V row layout (per b,i): ch' = c*1024 + j*16 + h (c-major) so thread t
// accesses offset c*1024 + t*4 -> warp-contiguous.
__device__ float g_V[(size_t)NB * NI * NO * CH];   // 256 MB
__device__ float g_S1b[3][NB * NO * CH];           // c-major layout per b
__device__ float g_S2b[3][NB * NO * CH];
__device__ float g_S0b[3][NB * NO];
__device__ float g_aoutb[3][NB * NO];
__device__ float g_nA[NB * NO * CH];               // -1/(2 sig2), c-major
__device__ float g_G[NB * NO * CH];                // mu/sig2,   c-major
__device__ float g_lac0[NB * NO];                  // log_sigmoid(a) - c0

// ---------------- f32x2 helpers ----------------
__device__ __forceinline__ ull pack2(float lo, float hi) {
    ull r; asm("mov.b64 %0, {%1, %2};" : "=l"(r) : "f"(lo), "f"(hi)); return r;
}
__device__ __forceinline__ void unpack2(ull v, float& lo, float& hi) {
    asm("mov.b64 {%0, %1}, %2;" : "=f"(lo), "=f"(hi) : "l"(v));
}
__device__ __forceinline__ ull fma2_3(ull a, ull b, ull c) {
    ull d; asm("fma.rn.f32x2 %0, %1, %2, %3;" : "=l"(d) : "l"(a), "l"(b), "l"(c)); return d;
}
__device__ __forceinline__ ull mul2(ull a, ull b) {
    ull d; asm("mul.rn.f32x2 %0, %1, %2;" : "=l"(d) : "l"(a), "l"(b)); return d;
}
__device__ __forceinline__ ull add2(ull a, ull b) {
    ull d; asm("add.rn.f32x2 %0, %1, %2;" : "=l"(d) : "l"(a), "l"(b)); return d;
}
__device__ __forceinline__ void fma2(ull& d, ull a, ull b) {
    asm("fma.rn.f32x2 %0, %1, %2, %0;" : "+l"(d) : "l"(a), "l"(b));
}

// ---------------- V generation (R13 version + bank-0 zeroing) ----------------
__global__ __launch_bounds__(256) void k_computeV(const float* __restrict__ mu,
                                                  const float* __restrict__ W,
                                                  const float* __restrict__ Bp) {
    int i = blockIdx.x;
    int t = threadIdx.x;

    // fold k_zero: blocks 0..255 zero moment bank 0 (iter0 launches after us)
    if (i < 256) {
        int idx = i * 256 + t;
        g_S1b[0][idx] = 0.f;
        g_S2b[0][idx] = 0.f;
        if (i < 4) {
            int idx2 = i * 256 + t;
            g_S0b[0][idx2] = 0.f;
            g_aoutb[0][idx2] = 0.f;
        }
    }

    __shared__ ull As2[64][16];

    for (int e = t; e < 1024; e += 256) {
        int m = e >> 4, d = e & 15;
        int b = m >> 2, c = m & 3;
        float val = mu[((size_t)b * NI + i) * 64 + c * 16 + d];
        As2[m][d] = pack2(val, val);
    }
    __syncthreads();

    int j = t >> 2;
    int q = t & 3;

    ull w01[16], w23[16];
    const float* Wi = W + (size_t)i * 16384;
    #pragma unroll
    for (int d = 0; d < 16; d++) {
        float4 w4 = *(const float4*)(Wi + j * 256 + d * 16 + q * 4);
        w01[d] = pack2(w4.x, w4.y);
        w23[d] = pack2(w4.z, w4.w);
    }
    ull b01[4], b23[4];
    const float* Bi = Bp + (size_t)i * 4096;
    #pragma unroll
    for (int c = 0; c < 4; c++) {
        float4 b4 = *(const float4*)(Bi + j * 64 + c * 16 + q * 4);
        b01[c] = pack2(b4.x, b4.y);
        b23[c] = pack2(b4.z, b4.w);
    }

    #pragma unroll 4
    for (int m = 0; m < 64; m++) {
        int bb = m >> 2, c = m & 3;
        ull a0 = b01[c], a1 = b23[c];
        #pragma unroll
        for (int d = 0; d < 16; d++) {
            ull aa = As2[m][d];
            fma2(a0, aa, w01[d]);
            fma2(a1, aa, w23[d]);
        }
        float4 r;
        unpack2(a0, r.x, r.y);
        unpack2(a1, r.z, r.w);
        size_t off = (size_t)bb * (NI * 4096ull) + (size_t)i * 4096
                   + (size_t)c * 1024 + (size_t)j * 16 + q * 4;   // c-major row
        *(float4*)(g_V + off) = r;
    }
}

// load this thread's 16 channels of a row: 4 coalesced float4 at c*1024 + t*4
__device__ __forceinline__ void load_row2(ull v[8], const float* row, int t) {
    #pragma unroll
    for (int c = 0; c < 4; c++) {
        float4 x = *(const float4*)(row + c * 1024 + t * 4);
        v[2*c]   = pack2(x.x, x.y);
        v[2*c+1] = pack2(x.z, x.w);
    }
}
__device__ __forceinline__ float sigmoidf_(float x) {
    return 1.f / (1.f + __expf(-x));
}

// ---------------- iteration 0: uniform R, tiles REVERSED (L2 zigzag) -------
__global__ __launch_bounds__(256) void k_iter0(const float* __restrict__ a_inp,
                                               const float* __restrict__ beta_use,
                                               const float* __restrict__ beta_ign) {
    int b    = blockIdx.x >> 5;
    int tile = 31 - (blockIdx.x & 31);   // reverse: start on freshest V
    int t    = threadIdx.x;

    __shared__ float bUs[TILE0 * 64], bIs[TILE0 * 64];   // 16 KB beta slice
    {
        const float4* bu4 = (const float4*)(beta_use + tile * TILE0 * 64);
        const float4* bi4 = (const float4*)(beta_ign + tile * TILE0 * 64);
        float4* u4 = (float4*)bUs; float4* i4 = (float4*)bIs;
        for (int idx = t; idx < TILE0 * 16; idx += 256) {
            u4[idx] = bu4[idx];
            i4[idx] = bi4[idx];
        }
    }
    __syncthreads();

    ull s1a[8], s2a[8];
    #pragma unroll
    for (int c = 0; c < 8; c++) { s1a[c] = pack2(0.f, 0.f); s2a[c] = s1a[c]; }
    float s0p = 0.f, aop = 0.f;

    const float* vb0 = g_V + (size_t)b * (NI * 4096ull);
    #pragma unroll 2
    for (int il = TILE0 - 1; il >= 0; il--) {    // descending i within tile
        int i = tile * TILE0 + il;
        ull v[8];
        load_row2(v, vb0 + (size_t)i * 4096, t);
        float fa = sigmoidf_(a_inp[b * NI + i]);
        float d = fa * (1.f / 64.f);
        ull d2 = pack2(d, d);
        #pragma unroll
        for (int c = 0; c < 8; c++) {
            fma2(s1a[c], v[c], d2);
            ull w = mul2(v[c], d2);
            fma2(s2a[c], w, v[c]);
        }
        if (t < 64) {
            s0p += d;
            aop += bUs[il * 64 + t] * d - bIs[il * 64 + t] * (fa - d);
        }
    }
    float* s1g = g_S1b[0] + b * 4096;
    float* s2g = g_S2b[0] + b * 4096;
    #pragma unroll
    for (int c = 0; c < 4; c++) {
        float lo, hi;
        int base = c * 1024 + t * 4;
        unpack2(s1a[2*c], lo, hi);
        atomicAdd(s1g + base + 0, lo); atomicAdd(s1g + base + 1, hi);
        unpack2(s1a[2*c+1], lo, hi);
        atomicAdd(s1g + base + 2, lo); atomicAdd(s1g + base + 3, hi);
        unpack2(s2a[2*c], lo, hi);
        atomicAdd(s2g + base + 0, lo); atomicAdd(s2g + base + 1, hi);
        unpack2(s2a[2*c+1], lo, hi);
        atomicAdd(s2g + base + 2, lo); atomicAdd(s2g + base + 3, hi);
    }
    if (t < 64) {
        atomicAdd(g_S0b[0] + b * 64 + t, s0p);
        atomicAdd(g_aoutb[0] + b * 64 + t, aop);
    }
}

// ---------------- coefficient kernel: bank SRC -> (-A, G, la-c0) -------------
// Also zeroes bank SRC+1 (which the next k_iter will accumulate into).
template<int SRC>
__global__ void k_coeff() {
    int bj = blockIdx.x;
    int b  = bj >> 6, j = bj & 63;
    int ch = threadIdx.x;
    int c  = ch >> 4, h = ch & 15;
    int idx = b * 4096 + c * 1024 + j * 16 + h;
    // zero next bank (flat index coverage: bj*64+ch spans 65536 exactly)
    g_S1b[SRC + 1][bj * 64 + ch] = 0.f;
    g_S2b[SRC + 1][bj * 64 + ch] = 0.f;
    if (ch == 0) {
        g_S0b[SRC + 1][bj] = 0.f;
        g_aoutb[SRC + 1][bj] = 0.f;
    }
    float S0 = g_S0b[SRC][bj];
    float over = 1.f / (S0 + EPSV);
    float s1 = g_S1b[SRC][idx];
    float s2 = g_S2b[SRC][idx];
    float m  = s1 * over;
    float sig2 = (s2 - 2.f * m * s1 + m * m * S0) * over + EPSV;
    float A = 0.5f / sig2;
    g_nA[idx] = -A;
    g_G[idx]  = m / sig2;
    float cc = m * m * A + 0.5f * logf(sig2);
    #pragma unroll
    for (int o = 16; o; o >>= 1) cc += __shfl_xor_sync(0xffffffffu, cc, o);
    __shared__ float red[2];
    if ((ch & 31) == 0) red[ch >> 5] = cc;
    __syncthreads();
    if (ch == 0) {
        float a = g_aoutb[SRC][bj];
        float la = fminf(a, 0.f) - log1pf(__expf(-fabsf(a)));
        g_lac0[bj] = la - (red[0] + red[1]);
    }
}

// logit partial over this thread's 16 channels
__device__ __forceinline__ float logit_part(const ull v[8], const ull nA2[8],
                                            const ull G2[8]) {
    ull s = pack2(0.f, 0.f);
    #pragma unroll
    for (int cp = 0; cp < 8; cp++) {
        ull tt = fma2_3(v[cp], nA2[cp], G2[cp]);
        s = fma2_3(v[cp], tt, s);
    }
    float lo, hi; unpack2(s, lo, hi);
    float r = lo + hi;
    r += __shfl_xor_sync(0xffffffffu, r, 1);
    r += __shfl_xor_sync(0xffffffffu, r, 2);
    return r;
}

// ---------------- iterations 1,2 (REV selects tile traversal direction) ------
// zigzag chain: computeV(i up) -> iter0(i down) -> iter1(i up) -> iter2(i down)
// Tail (s0/aout) handled by warp0 (row A) and warp1 (row B), reusing the exps
// they already computed in the redundant softmax reduction — zero extra MUFU.
template<int IT, int REV>
__global__ __launch_bounds__(256, 2) void k_iter(const float* __restrict__ a_inp,
                                                 const float* __restrict__ beta_use,
                                                 const float* __restrict__ beta_ign) {
    int b    = blockIdx.x >> 5;
    int tl   = blockIdx.x & 31;
    int tile = REV ? (31 - tl) : tl;
    int t    = threadIdx.x;
    int j4   = t >> 2;
    int part = t & 3;
    int lane = t & 31;
    int wid  = t >> 5;

    __shared__ float lbuf[2][2][64];
    __shared__ float bUs[TILE * 64], bIs[TILE * 64];    // 16 KB beta slice

    int ibase = tile * TILE;
    {
        const float4* bu4 = (const float4*)(beta_use + ibase * 64);
        const float4* bi4 = (const float4*)(beta_ign + ibase * 64);
        float4* u4 = (float4*)bUs; float4* i4 = (float4*)bIs;
        for (int idx = t; idx < TILE * 16; idx += 256) {
            u4[idx] = bu4[idx];
            i4[idx] = bi4[idx];
        }
    }

    ull nA2[8], G2[8];
    {
        const float* Ap = g_nA + b * 4096;
        const float* Gp = g_G + b * 4096;
        #pragma unroll
        for (int c = 0; c < 4; c++) {
            float4 av = *(const float4*)(Ap + c * 1024 + t * 4);
            float4 gv = *(const float4*)(Gp + c * 1024 + t * 4);
            nA2[2*c]   = pack2(av.x, av.y);
            nA2[2*c+1] = pack2(av.z, av.w);
            G2[2*c]    = pack2(gv.x, gv.y);
            G2[2*c+1]  = pack2(gv.z, gv.w);
        }
    }
    float lac0 = g_lac0[b * 64 + j4];

    ull s1a[8], s2a[8];
    #pragma unroll
    for (int c = 0; c < 8; c++) { s1a[c] = pack2(0.f, 0.f); s2a[c] = s1a[c]; }
    // tail accumulators: warp0 = row-A contributions for j = lane / lane+32,
    //                    warp1 = row-B contributions (others unused)
    float s0lo = 0.f, s0hi = 0.f, aolo = 0.f, aohi = 0.f;

    const float* vb0 = g_V + (size_t)b * (NI * 4096ull);

    ull va[8], vb[8];
    float faA, faB;
    load_row2(va, vb0 + (size_t)ibase * 4096, t);
    load_row2(vb, vb0 + (size_t)(ibase + 1) * 4096, t);
    faA = sigmoidf_(a_inp[b * NI + ibase]);
    faB = sigmoidf_(a_inp[b * NI + ibase + 1]);
    __syncthreads();   // beta staging visible before first tail use

    #pragma unroll 1
    for (int p = 0; p < TILE / 2; p++) {
        int pb = p & 1;
        float fcA = faA, fcB = faB;

        float lA = logit_part(va, nA2, G2);
        float lB = logit_part(vb, nA2, G2);
        if (part == 0) { lbuf[pb][0][j4] = lA + lac0; lbuf[pb][1][j4] = lB + lac0; }
        __syncthreads();

        float a0 = lbuf[pb][0][lane], a1 = lbuf[pb][0][lane + 32];
        float b0 = lbuf[pb][1][lane], b1 = lbuf[pb][1][lane + 32];
        float mxA = fmaxf(a0, a1), mxB = fmaxf(b0, b1);
        #pragma unroll
        for (int o = 16; o; o >>= 1) {
            mxA = fmaxf(mxA, __shfl_xor_sync(0xffffffffu, mxA, o));
            mxB = fmaxf(mxB, __shfl_xor_sync(0xffffffffu, mxB, o));
        }
        float e0A = __expf(a0 - mxA), e1A = __expf(a1 - mxA);
        float e0B = __expf(b0 - mxB), e1B = __expf(b1 - mxB);
        float ssA = e0A + e1A;
        float ssB = e0B + e1B;
        #pragma unroll
        for (int o = 16; o; o >>= 1) {
            ssA += __shfl_xor_sync(0xffffffffu, ssA, o);
            ssB += __shfl_xor_sync(0xffffffffu, ssB, o);
        }
        float invA = fcA / ssA, invB = fcB / ssB;
        float dA = __expf(lbuf[pb][0][j4] - mxA) * invA;
        float dB = __expf(lbuf[pb][1][j4] - mxB) * invB;

        // tail: reuse e0/e1 (no extra exps). warp0 -> row A, warp1 -> row B.
        if (wid == 0) {
            float dlo = e0A * invA, dhi = e1A * invA;
            s0lo += dlo; s0hi += dhi;
            int r0 = 2 * p * 64;
            aolo += bUs[r0 + lane]      * dlo - bIs[r0 + lane]      * (fcA - dlo);
            aohi += bUs[r0 + lane + 32] * dhi - bIs[r0 + lane + 32] * (fcA - dhi);
        } else if (wid == 1) {
            float dlo = e0B * invB, dhi = e1B * invB;
            s0lo += dlo; s0hi += dhi;
            int r1 = (2 * p + 1) * 64;
            aolo += bUs[r1 + lane]      * dlo - bIs[r1 + lane]      * (fcB - dlo);
            aohi += bUs[r1 + lane + 32] * dhi - bIs[r1 + lane + 32] * (fcB - dhi);
        }

        {
            ull d2 = pack2(dA, dA);
            #pragma unroll
            for (int c = 0; c < 8; c++) {
                fma2(s1a[c], va[c], d2);
                ull w = mul2(va[c], d2);
                fma2(s2a[c], w, va[c]);
            }
        }
        if (p < TILE / 2 - 1) {
            int nxt = ibase + 2 * p + 2;
            load_row2(va, vb0 + (size_t)nxt * 4096, t);
            faA = sigmoidf_(a_inp[b * NI + nxt]);
        }
        {
            ull d2 = pack2(dB, dB);
            #pragma unroll
            for (int c = 0; c < 8; c++) {
                fma2(s1a[c], vb[c], d2);
                ull w = mul2(vb[c], d2);
                fma2(s2a[c], w, vb[c]);
            }
        }
        if (p < TILE / 2 - 1) {
            int nxt = ibase + 2 * p + 3;
            load_row2(vb, vb0 + (size_t)nxt * 4096, t);
            faB = sigmoidf_(a_inp[b * NI + nxt]);
        }
    }

    float* s1g = g_S1b[IT] + b * 4096;
    float* s2g = g_S2b[IT] + b * 4096;
    #pragma unroll
    for (int c = 0; c < 4; c++) {
        float lo, hi;
        int base = c * 1024 + t * 4;
        unpack2(s1a[2*c], lo, hi);
        atomicAdd(s1g + base + 0, lo); atomicAdd(s1g + base + 1, hi);
        unpack2(s1a[2*c+1], lo, hi);
        atomicAdd(s1g + base + 2, lo); atomicAdd(s1g + base + 3, hi);
        unpack2(s2a[2*c], lo, hi);
        atomicAdd(s2g + base + 0, lo); atomicAdd(s2g + base + 1, hi);
        unpack2(s2a[2*c+1], lo, hi);
        atomicAdd(s2g + base + 2, lo); atomicAdd(s2g + base + 3, hi);
    }
    if (wid < 2) {
        atomicAdd(g_S0b[IT] + b * 64 + lane,      s0lo);
        atomicAdd(g_S0b[IT] + b * 64 + lane + 32, s0hi);
        atomicAdd(g_aoutb[IT] + b * 64 + lane,      aolo);
        atomicAdd(g_aoutb[IT] + b * 64 + lane + 32, aohi);
    }
}

// ---------------- final output from bank 2 (remap c-major -> j,c,h) ----------
__global__ void k_final(float* __restrict__ out) {
    int bj = blockIdx.x;
    int b  = bj >> 6, j = bj & 63;
    int ch = threadIdx.x;
    int c  = ch >> 4, h = ch & 15;
    int idx = b * 4096 + c * 1024 + j * 16 + h;
    float S0 = g_S0b[2][bj];
    float over = 1.f / (S0 + EPSV);
    float s1 = g_S1b[2][idx];
    float s2 = g_S2b[2][idx];
    float m  = s1 * over;
    float sig2 = (s2 - 2.f * m * s1 + m * m * S0) * over + EPSV;
    if (ch == 0) out[bj] = g_aoutb[2][bj];
    out[1024 + bj * 64 + ch] = m;
    out[1024 + NB * NO * CH + bj * 64 + ch] = sig2;
}

extern "C" void kernel_launch(void* const* d_in, const int* in_sizes, int n_in,
                              void* d_out, int out_size) {
    const float* a_inp = (const float*)d_in[0];
    const float* mu    = (const float*)d_in[1];
    const float* W     = (const float*)d_in[2];
    const float* Bp    = (const float*)d_in[3];
    const float* bu    = (const float*)d_in[4];
    const float* bi    = (const float*)d_in[5];
    float* out = (float*)d_out;

    k_computeV<<<NI, 256>>>(mu, W, Bp);          // writes V (i up), zeroes bank0
    k_iter0<<<NB * (NI / TILE0), 256>>>(a_inp, bu, bi);   // reads V, descending
    k_coeff<0><<<NB * NO, 64>>>();               // coeffs from bank0, zero bank1
    k_iter<1, 0><<<NB * (NI / TILE), 256>>>(a_inp, bu, bi); // ascending
    k_coeff<1><<<NB * NO, 64>>>();               // coeffs from bank1, zero bank2
    k_iter<2, 1><<<NB * (NI / TILE), 256>>>(a_inp, bu, bi); // descending
    k_final<<<NB * NO, 64>>>(out);
}